// round 7
// baseline (speedup 1.0000x reference)
#include <cuda_runtime.h>
#include <math.h>

#define BATCH   64
#define MAXN    128
#define GH      64
#define GW      32
#define NPTS    2048        // GH*GW
#define NSPLIT  16
#define MAXCHUNK 8          // ceil(MAXN / NSPLIT)
#define NTHREADS 256
#define PPT     8           // NPTS / NTHREADS

// Partial accumulators: [BATCH][NSPLIT][NPTS] complex (float2) = 16 MB
__device__ float2 g_partial[BATCH * NSPLIT * NPTS];

// pos_w[k] = float32(0.1 * (10^(1/30))^k), computed in double like numpy
__device__ __forceinline__ float pos_w_val(int k) {
    return (float)(0.1 * pow(10.0, (double)k / 30.0));
}

struct Tri { float xq, yq, xr, yr, xs, ys, area, scale2; };

__global__ __launch_bounds__(NTHREADS)
void pfc_accum_kernel(const float* __restrict__ tris,
                      const int* __restrict__ lengths) {
    __shared__ float sWx[GH];
    __shared__ float sWy[GW];
    __shared__ Tri   sTri[MAXCHUNK];
    // Tables: (cos, sin, lin, 0) per vertex phasor, factored row(h) x col(w).
    __shared__ float4 sRowQ[2][GH], sRowR[2][GH], sRowS[2][GH];
    __shared__ float4 sColQ[2][GW], sColR[2][GW], sColS[2][GW];

    const int tid = threadIdx.x;
    const int b   = blockIdx.x >> 4;        // / NSPLIT
    const int s   = blockIdx.x & (NSPLIT - 1);

    // Build frequency grid (once per block)
    if (tid < GH) {
        int h = tid;
        float v;
        if (h < 31)       v = -pos_w_val(30 - h);
        else if (h == 31) v = 0.0f;
        else if (h <= 62) v = pos_w_val(h - 32);
        else              v = 0.0f;           // padded row
        sWx[h] = v;
    } else if (tid < GH + GW) {
        int w = tid - GH;
        sWy[w] = (w == 0) ? 0.0f : pos_w_val(w - 1);
    }

    const float TWO_PI   = 6.28318530717958648f;
    const float FOUR_PI2 = 4.0f * 3.14159274101257324f * 3.14159274101257324f;

    const int len  = lengths[b];
    // interleaved assignment: this split owns triangles s, s+16, s+32, ...
    const int ntri = (len > s) ? ((len - 1 - s) / NSPLIT + 1) : 0;

    if (tid < MAXCHUNK && tid < ntri) {
        const int t = s + tid * NSPLIT;
        const float* p = tris + (size_t)(b * MAXN + t) * 6;
        Tri tr;
        tr.xq = p[0]; tr.yq = p[1];
        tr.xr = p[2]; tr.yr = p[3];
        tr.xs = p[4]; tr.ys = p[5];
        float det = tr.xq * (tr.yr - tr.ys) + tr.xr * (tr.ys - tr.yq)
                  + tr.xs * (tr.yq - tr.yr);
        tr.area   = fabsf(0.5f * det);
        tr.scale2 = 2.0f * tr.area / FOUR_PI2;
        sTri[tid] = tr;
    }
    __syncthreads();

    const int w     = tid & 31;
    const int hbase = (tid >> 5) * PPT;

    float accre[PPT], accim[PPT];
#pragma unroll
    for (int k = 0; k < PPT; k++) { accre[k] = 0.0f; accim[k] = 0.0f; }

    for (int j = 0; j < ntri; j++) {
        const Tri tr = sTri[j];   // broadcast
        const int buf = j & 1;

        // ---- build factored vertex-phasor tables (320 sincos, coop) ----
        if (tid < 192) {
            int h = tid & 63;
            int which = tid >> 6;               // 0:Q 1:R 2:S
            float wx = sWx[h];
            float arg, lin;
            if (which == 0)      { arg = wx * tr.xq; lin = wx * (tr.xr - tr.xq); }
            else if (which == 1) { arg = wx * tr.xr; lin = wx * (tr.xs - tr.xr); }
            else                 { arg = wx * tr.xs; lin = 0.0f; }
            float sn, cs;
            sincosf(-TWO_PI * arg, &sn, &cs);
            float4 v = make_float4(cs, sn, lin, 0.0f);
            if (which == 0)      sRowQ[buf][h] = v;
            else if (which == 1) sRowR[buf][h] = v;
            else                 sRowS[buf][h] = v;
        } else {
            int ww = tid & 31;
            float wy = sWy[ww];
            float arg, lin;
            if (tid < 224) { arg = wy * tr.yq; lin = wy * (tr.yr - tr.yq); }
            else           { arg = wy * tr.yr; lin = wy * (tr.ys - tr.yr); }
            float sn, cs;
            sincosf(-TWO_PI * arg, &sn, &cs);
            float4 v = make_float4(cs, sn, lin, 0.0f);
            if (tid < 224) sColQ[buf][ww] = v;
            else           sColR[buf][ww] = v;
        }
        if (tid < 32) {                         // second job: colS
            float wy = sWy[tid];
            float sn, cs;
            sincosf(-TWO_PI * (wy * tr.ys), &sn, &cs);
            sColS[buf][tid] = make_float4(cs, sn, 0.0f, 0.0f);
        }
        __syncthreads();   // single barrier per triangle (double buffered)

        const float4 cQ = sColQ[buf][w];
        const float4 cR = sColR[buf][w];
        const float4 cS = sColS[buf][w];
        const float area   = tr.area;
        const float scale2 = tr.scale2;

#pragma unroll
        for (int k = 0; k < PPT; k++) {
            const int h = hbase + k;            // uniform across the warp
            const float4 rQ = sRowQ[buf][h];
            const float4 rR = sRowR[buf][h];
            const float4 rS = sRowS[buf][h];

            const float U_ = rQ.z + cQ.z;       // row lin + col lin
            const float V_ = rR.z + cR.z;
            const float S  = U_ + V_;

            // vertex phasors: row x col unit-complex products
            const float eqR = rQ.x * cQ.x - rQ.y * cQ.y;
            const float eqI = rQ.x * cQ.y + rQ.y * cQ.x;
            const float erR = rR.x * cR.x - rR.y * cR.y;
            const float erI = rR.x * cR.y + rR.y * cR.x;
            const float esR = rS.x * cS.x - rS.y * cS.y;
            const float esI = rS.x * cS.y + rS.y * cS.x;

            // ---- branchless case selection (mirrors reference masks) ----
            const bool u0 = (U_ == 0.0f);
            const bool v0 = (V_ == 0.0f);
            const bool s0 = (S  == 0.0f);
            const bool zero = u0 && v0;
            const bool diag = s0 && !zero;
            const bool um   = u0 && !zero;
            const bool vm   = v0 && !zero;
            const bool sp   = diag || um || vm;

            // p2 = A*Es + B*Er + C*Eq + i*(w1*Eq + w2*Er)
            const float A  = sp ? (um ? 1.0f : 0.0f) : -U_;
            const float B  = sp ? (um ? 0.0f : 1.0f) : S;
            const float C  = sp ? -1.0f : -V_;
            const float w1 = diag ? (TWO_PI * U_) : (um ? (TWO_PI * V_) : 0.0f);
            const float w2 = vm ? (TWO_PI * U_) : 0.0f;
            float den = sp ? (um ? -(V_ * V_) : (diag ? -(U_ * U_) : U_ * U_))
                           : (U_ * V_ * S);
            den = zero ? 1.0f : den;
            const float scale = __fdividef(scale2, den);

            const float p2re = A * esR + B * erR + C * eqR - w1 * eqI - w2 * erI;
            const float p2im = A * esI + B * erI + C * eqI + w1 * eqR + w2 * erR;

            float tre = scale * p2re;
            float tim = scale * p2im;
            tre = zero ? area : tre;
            tim = zero ? 0.0f : tim;
            accre[k] += tre;
            accim[k] += tim;
        }
        // next build writes the other buffer; the barrier at the top of
        // iteration j+1 orders build(j+2) after eval(j).
    }

#pragma unroll
    for (int k = 0; k < PPT; k++) {
        const int p = (hbase + k) * GW + w;
        g_partial[(b * NSPLIT + s) * NPTS + p] = make_float2(accre[k], accim[k]);
    }
}

__global__ __launch_bounds__(128)
void pfc_finalize_kernel(float* __restrict__ out) {
    const int idx = blockIdx.x * 128 + threadIdx.x;   // 0 .. BATCH*NPTS-1
    if (idx >= BATCH * NPTS) return;
    const int b = idx / NPTS;
    const int p = idx % NPTS;
    const int h = p >> 5;

    float re = 0.0f, im = 0.0f;
#pragma unroll
    for (int s = 0; s < NSPLIT; s++) {
        float2 v = g_partial[(b * NSPLIT + s) * NPTS + p];
        re += v.x; im += v.y;
    }

    float mag, phase;
    const float m2 = re * re + im * im;
    if (h == GH - 1 || m2 == 0.0f) {      // padded row, or zero total
        mag = 0.0f; phase = 0.0f;
    } else {
        mag   = log1pf(sqrtf(m2));
        phase = atan2f(im, re);
    }
    out[idx] = mag;                        // mag  block: [B,1,GH,GW]
    out[BATCH * NPTS + idx] = phase;       // phase block: [B,1,GH,GW]
}

extern "C" void kernel_launch(void* const* d_in, const int* in_sizes, int n_in,
                              void* d_out, int out_size) {
    const float* tris    = (const float*)d_in[0];   // [64,128,3,2] f32
    const int*   lengths = (const int*)d_in[1];     // [64] i32
    float* out = (float*)d_out;                     // 262144 f32: mag then phase

    pfc_accum_kernel<<<BATCH * NSPLIT, NTHREADS>>>(tris, lengths);
    pfc_finalize_kernel<<<(BATCH * NPTS + 127) / 128, 128>>>(out);
}